// round 2
// baseline (speedup 1.0000x reference)
#include <cuda_runtime.h>
#include <math_constants.h>

#define E_TOT 50000
#define DD 128
#define HH 256
#define BB 8
#define KTOP 10
#define TILE_E 64
#define TK 64

__device__ float g_ph[BB * HH];
__device__ float g_scores[BB * E_TOT];

// ---------------------------------------------------------------------------
// Kernel 1: ph[b][h] = sum_d h_emb[d]*W1[d][h] + r_emb[d]*W1[128+d][h] + b1[h]
// grid (8), block (256)
// ---------------------------------------------------------------------------
__global__ void ph_kernel(const int* __restrict__ head, const int* __restrict__ rel,
                          const float* __restrict__ ent, const float* __restrict__ relm,
                          const float* __restrict__ W1, const float* __restrict__ b1) {
    int b = blockIdx.x;
    int h = threadIdx.x;
    const float* hrow = ent + (size_t)head[b] * DD;
    const float* rrow = relm + (size_t)rel[b] * DD;
    float acc = b1[h];
#pragma unroll 4
    for (int d = 0; d < DD; ++d) {
        acc = fmaf(hrow[d], W1[d * HH + h], acc);
        acc = fmaf(rrow[d], W1[(DD + d) * HH + h], acc);
    }
    g_ph[b * HH + h] = acc;
}

// ---------------------------------------------------------------------------
// Kernel 2: fused pt-GEMM + relu-score.
// One CTA per 64-entity tile. 256 threads, 8x8 register micro-tile.
// tx = tid&31 covers h = tx*8..tx*8+7 (256 h total per warp of 32 lanes)
// ty = tid>>5 covers e = e_base + ty*8 .. +7 (64 e total per 8 warps)
// ---------------------------------------------------------------------------
extern __shared__ float smem[];

__global__ __launch_bounds__(256, 2)
void score_kernel(const float* __restrict__ ent, const float* __restrict__ W1,
                  const float* __restrict__ W2, const float* __restrict__ b2) {
    float* ent_s  = smem;                         // TILE_E * DD       = 8192 f
    float* w1t_s  = ent_s + TILE_E * DD;          // TK * HH           = 16384 f
    float* ph_s   = w1t_s + TK * HH;              // BB * HH           = 2048 f
    float* w2_s   = ph_s + BB * HH;               // HH                = 256 f

    const int tid = threadIdx.x;
    const int e_base = blockIdx.x * TILE_E;

    // stage entity tile (zero-fill out-of-range rows)
    for (int idx = tid; idx < TILE_E * DD / 4; idx += 256) {
        int e  = idx / (DD / 4);
        int d4 = idx % (DD / 4);
        float4 v = make_float4(0.f, 0.f, 0.f, 0.f);
        if (e_base + e < E_TOT)
            v = *(const float4*)(ent + (size_t)(e_base + e) * DD + d4 * 4);
        *(float4*)(ent_s + e * DD + d4 * 4) = v;
    }
    // stage ph and W2
    for (int idx = tid; idx < BB * HH; idx += 256) ph_s[idx] = g_ph[idx];
    w2_s[tid] = W2[tid];

    const int tx = tid & 31;
    const int ty = tid >> 5;

    float acc[8][8];
#pragma unroll
    for (int i = 0; i < 8; ++i)
#pragma unroll
        for (int j = 0; j < 8; ++j) acc[i][j] = 0.f;

    const float* W1t = W1 + 2 * DD * HH;   // rows [256, 384) of W1

    for (int kt = 0; kt < DD / TK; ++kt) {
        __syncthreads();
        // stage W1t rows [kt*TK, kt*TK+TK)
        for (int idx = tid; idx < TK * HH / 4; idx += 256) {
            *(float4*)(w1t_s + idx * 4) =
                *(const float4*)(W1t + kt * TK * HH + idx * 4);
        }
        __syncthreads();

#pragma unroll 4
        for (int dd = 0; dd < TK; ++dd) {
            int d = kt * TK + dd;
            float w[8];
            *(float4*)&w[0] = *(float4*)(w1t_s + dd * HH + tx * 8);
            *(float4*)&w[4] = *(float4*)(w1t_s + dd * HH + tx * 8 + 4);
#pragma unroll
            for (int i = 0; i < 8; ++i) {
                float a = ent_s[(ty * 8 + i) * DD + d];
#pragma unroll
                for (int j = 0; j < 8; ++j)
                    acc[i][j] = fmaf(a, w[j], acc[i][j]);
            }
        }
    }

    // epilogue: scores[b][e] = sum_h relu(ph[b][h] + pt[e][h]) * W2[h] + b2
    const float b2v = b2[0];
    float w2v[8];
    *(float4*)&w2v[0] = *(float4*)(w2_s + tx * 8);
    *(float4*)&w2v[4] = *(float4*)(w2_s + tx * 8 + 4);

#pragma unroll
    for (int b = 0; b < BB; ++b) {
        float phv[8];
        *(float4*)&phv[0] = *(float4*)(ph_s + b * HH + tx * 8);
        *(float4*)&phv[4] = *(float4*)(ph_s + b * HH + tx * 8 + 4);
#pragma unroll
        for (int i = 0; i < 8; ++i) {
            float s = 0.f;
#pragma unroll
            for (int j = 0; j < 8; ++j)
                s = fmaf(fmaxf(acc[i][j] + phv[j], 0.f), w2v[j], s);
            // reduce across 32 lanes (full h dimension)
#pragma unroll
            for (int off = 16; off > 0; off >>= 1)
                s += __shfl_xor_sync(0xffffffffu, s, off);
            int e = e_base + ty * 8 + i;
            if (tx == 0 && e < E_TOT)
                g_scores[b * E_TOT + e] = s + b2v;
        }
    }
}

// ---------------------------------------------------------------------------
// Kernel 3: per-batch top-10. grid (8), block (256).
// Tie-break: lower index wins on equal scores (matches jax.lax.top_k).
// Output: out[0:80] = indices (as float), out[80:160] = scores.
// ---------------------------------------------------------------------------
__global__ void topk_kernel(float* __restrict__ out) {
    const int b = blockIdx.x;
    const int tid = threadIdx.x;

    float sc[KTOP];
    int   si[KTOP];
#pragma unroll
    for (int j = 0; j < KTOP; ++j) { sc[j] = -CUDART_INF_F; si[j] = 0x7fffffff; }

    const float* row = g_scores + (size_t)b * E_TOT;
    for (int e = tid; e < E_TOT; e += 256) {
        float s = row[e];
        if (s > sc[KTOP - 1]) {     // strict: equal-score keeps earlier (lower) index
            int p = KTOP - 1;
            while (p > 0 && s > sc[p - 1]) {
                sc[p] = sc[p - 1];
                si[p] = si[p - 1];
                --p;
            }
            sc[p] = s; si[p] = e;
        }
    }

    __shared__ float ssc[256 * KTOP];
    __shared__ int   ssi[256 * KTOP];
#pragma unroll
    for (int j = 0; j < KTOP; ++j) { ssc[tid * KTOP + j] = sc[j]; ssi[tid * KTOP + j] = si[j]; }
    __syncthreads();

    for (int stride = 128; stride > 0; stride >>= 1) {
        if (tid < stride) {
            float* A  = &ssc[tid * KTOP];
            int*   Ai = &ssi[tid * KTOP];
            float* Bv = &ssc[(tid + stride) * KTOP];
            int*   Bi = &ssi[(tid + stride) * KTOP];
            float msc[KTOP]; int msi[KTOP];
            int p = 0, q = 0;
#pragma unroll
            for (int j = 0; j < KTOP; ++j) {
                bool takeA = (A[p] > Bv[q]) || (A[p] == Bv[q] && Ai[p] < Bi[q]);
                if (takeA) { msc[j] = A[p]; msi[j] = Ai[p]; ++p; }
                else       { msc[j] = Bv[q]; msi[j] = Bi[q]; ++q; }
            }
#pragma unroll
            for (int j = 0; j < KTOP; ++j) { A[j] = msc[j]; Ai[j] = msi[j]; }
        }
        __syncthreads();
    }

    if (tid < KTOP) {
        out[b * KTOP + tid]             = (float)ssi[tid];   // top_indices block
        out[BB * KTOP + b * KTOP + tid] = ssc[tid];          // top_scores block
    }
}

// ---------------------------------------------------------------------------
extern "C" void kernel_launch(void* const* d_in, const int* in_sizes, int n_in,
                              void* d_out, int out_size) {
    // Input order per setup_inputs: head, relation, [k], ent_emb, rel_emb, W1, b1, W2, b2
    // Hedge: scalar k may or may not be materialized as an input.
    int base = (n_in >= 3 && in_sizes[2] == 1) ? 3 : 2;

    const int*   head = (const int*)d_in[0];
    const int*   rel  = (const int*)d_in[1];
    const float* ent  = (const float*)d_in[base + 0];
    const float* relm = (const float*)d_in[base + 1];
    const float* W1   = (const float*)d_in[base + 2];
    const float* b1   = (const float*)d_in[base + 3];
    const float* W2   = (const float*)d_in[base + 4];
    const float* b2   = (const float*)d_in[base + 5];
    float* out = (float*)d_out;

    size_t smem_bytes = (size_t)(TILE_E * DD + TK * HH + BB * HH + HH) * sizeof(float);
    cudaFuncSetAttribute(score_kernel, cudaFuncAttributeMaxDynamicSharedMemorySize,
                         (int)smem_bytes);

    ph_kernel<<<BB, HH>>>(head, rel, ent, relm, W1, b1);
    score_kernel<<<(E_TOT + TILE_E - 1) / TILE_E, 256, smem_bytes>>>(ent, W1, W2, b2);
    topk_kernel<<<BB, 256>>>(out);
}

// round 3
// speedup vs baseline: 1.8810x; 1.8810x over previous
#include <cuda_runtime.h>
#include <math_constants.h>

#define E_TOT 50000
#define DD 128
#define HH 256
#define BB 8
#define KTOP 10
#define TILE_E 64
#define TK 64
#define NCHUNK 16   // topk stage-1 chunks per batch

__device__ float g_ph[BB * HH];
__device__ float g_scores[BB * E_TOT];
__device__ float g_cs[BB * NCHUNK * KTOP];
__device__ int   g_ci[BB * NCHUNK * KTOP];

// ---------------------------------------------------------------------------
// Kernel 1: ph[b][h] = sum_d h_emb[d]*W1[d][h] + r_emb[d]*W1[128+d][h] + b1[h]
// grid (8,4) block 256: blockIdx.y picks 64 h; tid = dq*64 + hl (dq: 32-d slice)
// ---------------------------------------------------------------------------
__global__ void ph_kernel(const int* __restrict__ head, const int* __restrict__ rel,
                          const float* __restrict__ ent, const float* __restrict__ relm,
                          const float* __restrict__ W1, const float* __restrict__ b1) {
    __shared__ float red[4 * 64];
    const int b  = blockIdx.x;
    const int hl = threadIdx.x & 63;
    const int dq = threadIdx.x >> 6;          // 0..3
    const int h  = blockIdx.y * 64 + hl;

    const float* hrow = ent  + (size_t)head[b] * DD;
    const float* rrow = relm + (size_t)rel[b] * DD;

    float acc = 0.f;
#pragma unroll 8
    for (int dd = 0; dd < 32; ++dd) {
        int d = dq * 32 + dd;
        acc = fmaf(hrow[d], W1[d * HH + h], acc);
        acc = fmaf(rrow[d], W1[(DD + d) * HH + h], acc);
    }
    red[dq * 64 + hl] = acc;
    __syncthreads();
    if (threadIdx.x < 64) {
        float s = red[hl] + red[64 + hl] + red[128 + hl] + red[192 + hl] + b1[h];
        g_ph[b * HH + h] = s;
    }
}

// ---------------------------------------------------------------------------
// Kernel 2: fused pt-GEMM + relu-score.
// One CTA per 64-entity tile. 256 threads, 8x8 register micro-tile.
// lane tx owns h in {tx*4..tx*4+3} U {128+tx*4..128+tx*4+3}  (conflict-free)
// warp ty owns e = e_base + ty*8 .. +7
// ent tile staged TRANSPOSED: ent_sT[d][e]  -> a loads are 2 broadcast LDS.128
// ---------------------------------------------------------------------------
extern __shared__ float smem[];

__global__ __launch_bounds__(256, 2)
void score_kernel(const float* __restrict__ ent, const float* __restrict__ W1,
                  const float* __restrict__ W2, const float* __restrict__ b2) {
    float* ent_sT = smem;                         // DD * TILE_E = 8192 f (32KB)
    float* w1t_s  = ent_sT + DD * TILE_E;         // TK * HH     = 16384 f (64KB)
    float* ph_s   = w1t_s + TK * HH;              // BB * HH     = 2048 f
    float* w2_s   = ph_s + BB * HH;               // HH          = 256 f

    const int tid = threadIdx.x;
    const int e_base = blockIdx.x * TILE_E;

    // stage entity tile transposed. idx = d4*64 + e : warp lanes span e
    // -> smem write bank = e mod 32 : conflict-free scalar stores.
    for (int idx = tid; idx < (DD / 4) * TILE_E; idx += 256) {
        int d4 = idx >> 6;            // 0..31
        int e  = idx & 63;
        float4 v = make_float4(0.f, 0.f, 0.f, 0.f);
        if (e_base + e < E_TOT)
            v = *(const float4*)(ent + (size_t)(e_base + e) * DD + d4 * 4);
        ent_sT[(d4 * 4 + 0) * TILE_E + e] = v.x;
        ent_sT[(d4 * 4 + 1) * TILE_E + e] = v.y;
        ent_sT[(d4 * 4 + 2) * TILE_E + e] = v.z;
        ent_sT[(d4 * 4 + 3) * TILE_E + e] = v.w;
    }
    for (int idx = tid; idx < BB * HH; idx += 256) ph_s[idx] = g_ph[idx];
    w2_s[tid] = W2[tid];

    const int tx = tid & 31;
    const int ty = tid >> 5;

    float acc[8][8];
#pragma unroll
    for (int i = 0; i < 8; ++i)
#pragma unroll
        for (int j = 0; j < 8; ++j) acc[i][j] = 0.f;

    const float* W1t = W1 + 2 * DD * HH;   // rows [256, 384) of W1

    for (int kt = 0; kt < DD / TK; ++kt) {
        __syncthreads();
        for (int idx = tid; idx < TK * HH / 4; idx += 256) {
            *(float4*)(w1t_s + idx * 4) =
                *(const float4*)(W1t + kt * TK * HH + idx * 4);
        }
        __syncthreads();

#pragma unroll 2
        for (int dd = 0; dd < TK; ++dd) {
            const int d = kt * TK + dd;
            float w[8], a[8];
            *(float4*)&w[0] = *(float4*)(w1t_s + dd * HH + tx * 4);        // h = tx*4..+3
            *(float4*)&w[4] = *(float4*)(w1t_s + dd * HH + 128 + tx * 4);  // h = 128+tx*4..+3
            *(float4*)&a[0] = *(float4*)(ent_sT + d * TILE_E + ty * 8);    // broadcast
            *(float4*)&a[4] = *(float4*)(ent_sT + d * TILE_E + ty * 8 + 4);
#pragma unroll
            for (int i = 0; i < 8; ++i)
#pragma unroll
                for (int j = 0; j < 8; ++j)
                    acc[i][j] = fmaf(a[i], w[j], acc[i][j]);
        }
    }

    // epilogue: scores[b][e] = sum_h relu(ph[b][h] + pt[e][h]) * W2[h] + b2
    const float b2v = b2[0];
    float w2v[8];
    *(float4*)&w2v[0] = *(float4*)(w2_s + tx * 4);
    *(float4*)&w2v[4] = *(float4*)(w2_s + 128 + tx * 4);

#pragma unroll
    for (int b = 0; b < BB; ++b) {
        float phv[8];
        *(float4*)&phv[0] = *(float4*)(ph_s + b * HH + tx * 4);
        *(float4*)&phv[4] = *(float4*)(ph_s + b * HH + 128 + tx * 4);
#pragma unroll
        for (int i = 0; i < 8; ++i) {
            float s = 0.f;
#pragma unroll
            for (int j = 0; j < 8; ++j)
                s = fmaf(fmaxf(acc[i][j] + phv[j], 0.f), w2v[j], s);
#pragma unroll
            for (int off = 16; off > 0; off >>= 1)
                s += __shfl_xor_sync(0xffffffffu, s, off);
            int e = e_base + ty * 8 + i;
            if (tx == 0 && e < E_TOT)
                g_scores[b * E_TOT + e] = s + b2v;
        }
    }
}

// ---------------------------------------------------------------------------
// Kernel 3a: per-(batch, chunk) top-10 into candidate buffer.
// grid (8, 16), block 256. chunk = 3125 entities.
// ---------------------------------------------------------------------------
__global__ void topk1_kernel() {
    const int b = blockIdx.x;
    const int c = blockIdx.y;
    const int tid = threadIdx.x;
    const int cbeg = c * (E_TOT / NCHUNK);
    const int cend = cbeg + (E_TOT / NCHUNK);

    float sc[KTOP];
    int   si[KTOP];
#pragma unroll
    for (int j = 0; j < KTOP; ++j) { sc[j] = -CUDART_INF_F; si[j] = 0x7fffffff; }

    const float* row = g_scores + (size_t)b * E_TOT;
    for (int e = cbeg + tid; e < cend; e += 256) {
        float s = row[e];
        if (s > sc[KTOP - 1]) {
            int p = KTOP - 1;
            while (p > 0 && s > sc[p - 1]) { sc[p] = sc[p - 1]; si[p] = si[p - 1]; --p; }
            sc[p] = s; si[p] = e;
        }
    }

    __shared__ float ssc[256 * KTOP];
    __shared__ int   ssi[256 * KTOP];
#pragma unroll
    for (int j = 0; j < KTOP; ++j) { ssc[tid * KTOP + j] = sc[j]; ssi[tid * KTOP + j] = si[j]; }
    __syncthreads();

    for (int stride = 128; stride > 0; stride >>= 1) {
        if (tid < stride) {
            float* A  = &ssc[tid * KTOP];
            int*   Ai = &ssi[tid * KTOP];
            float* Bv = &ssc[(tid + stride) * KTOP];
            int*   Bi = &ssi[(tid + stride) * KTOP];
            float msc[KTOP]; int msi[KTOP];
            int p = 0, q = 0;
#pragma unroll
            for (int j = 0; j < KTOP; ++j) {
                bool takeA = (A[p] > Bv[q]) || (A[p] == Bv[q] && Ai[p] < Bi[q]);
                if (takeA) { msc[j] = A[p]; msi[j] = Ai[p]; ++p; }
                else       { msc[j] = Bv[q]; msi[j] = Bi[q]; ++q; }
            }
#pragma unroll
            for (int j = 0; j < KTOP; ++j) { A[j] = msc[j]; Ai[j] = msi[j]; }
        }
        __syncthreads();
    }

    if (tid < KTOP) {
        g_cs[(b * NCHUNK + c) * KTOP + tid] = ssc[tid];
        g_ci[(b * NCHUNK + c) * KTOP + tid] = ssi[tid];
    }
}

// ---------------------------------------------------------------------------
// Kernel 3b: merge 160 candidates per batch via 256-wide bitonic sort.
// Comparator: score desc, index asc (matches jax.lax.top_k tie-break).
// Output: out[0:80] = indices (as float), out[80:160] = scores.
// ---------------------------------------------------------------------------
__global__ void topk2_kernel(float* __restrict__ out) {
    const int b = blockIdx.x;
    const int tid = threadIdx.x;
    __shared__ float ss[256];
    __shared__ int   si[256];

    if (tid < NCHUNK * KTOP) {
        ss[tid] = g_cs[b * NCHUNK * KTOP + tid];
        si[tid] = g_ci[b * NCHUNK * KTOP + tid];
    } else {
        ss[tid] = -CUDART_INF_F;
        si[tid] = 0x7fffffff;
    }
    __syncthreads();

    for (int k = 2; k <= 256; k <<= 1) {
        for (int j = k >> 1; j > 0; j >>= 1) {
            int ixj = tid ^ j;
            if (ixj > tid) {
                bool up = ((tid & k) == 0);   // 'up' = this run sorted best-first
                float s1 = ss[tid], s2 = ss[ixj];
                int   i1 = si[tid], i2 = si[ixj];
                bool ahead = (s1 > s2) || (s1 == s2 && i1 < i2);
                if (ahead != up) {            // swap
                    ss[tid] = s2; si[tid] = i2;
                    ss[ixj] = s1; si[ixj] = i1;
                }
            }
            __syncthreads();
        }
    }

    if (tid < KTOP) {
        out[b * KTOP + tid]             = (float)si[tid];   // top_indices
        out[BB * KTOP + b * KTOP + tid] = ss[tid];          // top_scores
    }
}

// ---------------------------------------------------------------------------
extern "C" void kernel_launch(void* const* d_in, const int* in_sizes, int n_in,
                              void* d_out, int out_size) {
    int base = (n_in >= 3 && in_sizes[2] == 1) ? 3 : 2;

    const int*   head = (const int*)d_in[0];
    const int*   rel  = (const int*)d_in[1];
    const float* ent  = (const float*)d_in[base + 0];
    const float* relm = (const float*)d_in[base + 1];
    const float* W1   = (const float*)d_in[base + 2];
    const float* b1   = (const float*)d_in[base + 3];
    const float* W2   = (const float*)d_in[base + 4];
    const float* b2   = (const float*)d_in[base + 5];
    float* out = (float*)d_out;

    size_t smem_bytes = (size_t)(DD * TILE_E + TK * HH + BB * HH + HH) * sizeof(float);
    cudaFuncSetAttribute(score_kernel, cudaFuncAttributeMaxDynamicSharedMemorySize,
                         (int)smem_bytes);

    ph_kernel<<<dim3(BB, 4), 256>>>(head, rel, ent, relm, W1, b1);
    score_kernel<<<(E_TOT + TILE_E - 1) / TILE_E, 256, smem_bytes>>>(ent, W1, W2, b2);
    topk1_kernel<<<dim3(BB, NCHUNK), 256>>>();
    topk2_kernel<<<BB, 256>>>(out);
}

// round 5
// speedup vs baseline: 2.0806x; 1.1061x over previous
#include <cuda_runtime.h>
#include <math_constants.h>
#include <cstdint>

#define E_TOT 50000
#define E_PAD 50048
#define DD 128
#define HH 256
#define BB 8
#define KTOP 10
#define TILE_M 128
#define NCHUNK 16
#define N_TILES ((E_TOT + TILE_M - 1) / TILE_M)   // 391

__device__ float g_ph[BB * HH];
__device__ float g_part[4][BB][E_PAD];
__device__ float g_cs[BB * NCHUNK * KTOP];
__device__ int   g_ci[BB * NCHUNK * KTOP];

// ---------------------------------------------------------------------------
__device__ __forceinline__ float tf32_rna(float x) {
    uint32_t u;
    asm("cvt.rna.tf32.f32 %0, %1;" : "=r"(u) : "f"(x));
    return __uint_as_float(u);
}
__device__ __forceinline__ void mma_tf32(float c[4], const uint32_t a[4],
                                         uint32_t b0, uint32_t b1) {
    asm volatile(
        "mma.sync.aligned.m16n8k8.row.col.f32.tf32.tf32.f32 "
        "{%0,%1,%2,%3}, {%4,%5,%6,%7}, {%8,%9}, {%0,%1,%2,%3};"
        : "+f"(c[0]), "+f"(c[1]), "+f"(c[2]), "+f"(c[3])
        : "r"(a[0]), "r"(a[1]), "r"(a[2]), "r"(a[3]), "r"(b0), "r"(b1));
}

// ---------------------------------------------------------------------------
// Kernel 1: ph[b][h]
// ---------------------------------------------------------------------------
__global__ void ph_kernel(const int* __restrict__ head, const int* __restrict__ rel,
                          const float* __restrict__ ent, const float* __restrict__ relm,
                          const float* __restrict__ W1, const float* __restrict__ b1) {
    __shared__ float red[4 * 64];
    const int b  = blockIdx.x;
    const int hl = threadIdx.x & 63;
    const int dq = threadIdx.x >> 6;
    const int h  = blockIdx.y * 64 + hl;
    const float* hrow = ent  + (size_t)head[b] * DD;
    const float* rrow = relm + (size_t)rel[b] * DD;
    float acc = 0.f;
#pragma unroll 8
    for (int dd = 0; dd < 32; ++dd) {
        int d = dq * 32 + dd;
        acc = fmaf(hrow[d], W1[d * HH + h], acc);
        acc = fmaf(rrow[d], W1[(DD + d) * HH + h], acc);
    }
    red[dq * 64 + hl] = acc;
    __syncthreads();
    if (threadIdx.x < 64)
        g_ph[b * HH + h] = red[hl] + red[64 + hl] + red[128 + hl] + red[192 + hl] + b1[h];
}

// ---------------------------------------------------------------------------
// Kernel 2: 3xTF32 mma.sync GEMM + fused relu-score epilogue on C-fragments.
// grid (391, 2): x = 128-entity tile, y = n-half (128 of 256 h).
// 8 warps: mw = wid&3 (m: rows mw*32), nw = wid>>2 (n: cols nw*64).
// Warp tile 32(m) x 64(n): acc[2 mt][8 nt][4].
// ---------------------------------------------------------------------------
#define A_STRIDE 36      // 32 k + 4 pad  -> fragment LDS conflict-free
#define B_STRIDE 136     // 128 n + 8 pad -> fragment LDS conflict-free
#define SM_AH 0
#define SM_AL (128 * A_STRIDE)
#define SM_BH (2 * 128 * A_STRIDE)
#define SM_BL (2 * 128 * A_STRIDE + 32 * B_STRIDE)
#define SM_PH (2 * 128 * A_STRIDE + 2 * 32 * B_STRIDE)
#define SM_W2 (SM_PH + BB * 128)
#define SM_TOT_F (SM_W2 + 128)

extern __shared__ float sm[];

__global__ __launch_bounds__(256, 2)
void score_kernel(const float* __restrict__ ent, const float* __restrict__ W1,
                  const float* __restrict__ W2) {
    const int tid = threadIdx.x;
    const int wid = tid >> 5;
    const int lid = tid & 31;
    const int gID = lid >> 2;          // 0..7
    const int tig = lid & 3;           // 0..3
    const int mw  = wid & 3;
    const int nw  = wid >> 2;
    const int e_base = blockIdx.x * TILE_M;
    const int nh = blockIdx.y;

    float* Ah = sm + SM_AH;
    float* Al = sm + SM_AL;
    float* Bh = sm + SM_BH;
    float* Bl = sm + SM_BL;
    float* ph_s = sm + SM_PH;
    float* w2_s = sm + SM_W2;

    for (int idx = tid; idx < BB * 128; idx += 256) {
        int b = idx >> 7, col = idx & 127;
        ph_s[idx] = g_ph[b * HH + nh * 128 + col];
    }
    if (tid < 128) w2_s[tid] = W2[nh * 128 + tid];

    float acc[2][8][4];
#pragma unroll
    for (int mt = 0; mt < 2; ++mt)
#pragma unroll
        for (int nt = 0; nt < 8; ++nt)
#pragma unroll
            for (int q = 0; q < 4; ++q) acc[mt][nt][q] = 0.f;

    const float* W1t = W1 + 2 * DD * HH;

    for (int c = 0; c < 4; ++c) {
        __syncthreads();
        // ---- stage A chunk (128 m x 32 k), tf32 hi/lo ----
#pragma unroll
        for (int it = 0; it < 4; ++it) {
            int idx = it * 256 + tid;
            int m  = idx >> 3;
            int k4 = idx & 7;
            float4 v = make_float4(0.f, 0.f, 0.f, 0.f);
            if (e_base + m < E_TOT)
                v = *(const float4*)(ent + (size_t)(e_base + m) * DD + c * 32 + k4 * 4);
            float4 h, l;
            h.x = tf32_rna(v.x); l.x = tf32_rna(v.x - h.x);
            h.y = tf32_rna(v.y); l.y = tf32_rna(v.y - h.y);
            h.z = tf32_rna(v.z); l.z = tf32_rna(v.z - h.z);
            h.w = tf32_rna(v.w); l.w = tf32_rna(v.w - h.w);
            *(float4*)(Ah + m * A_STRIDE + k4 * 4) = h;
            *(float4*)(Al + m * A_STRIDE + k4 * 4) = l;
        }
        // ---- stage B chunk (32 k x 128 n), tf32 hi/lo ----
#pragma unroll
        for (int it = 0; it < 4; ++it) {
            int idx = it * 256 + tid;
            int kk = idx >> 5;
            int n4 = idx & 31;
            float4 v = *(const float4*)(W1t + (size_t)(c * 32 + kk) * HH + nh * 128 + n4 * 4);
            float4 h, l;
            h.x = tf32_rna(v.x); l.x = tf32_rna(v.x - h.x);
            h.y = tf32_rna(v.y); l.y = tf32_rna(v.y - h.y);
            h.z = tf32_rna(v.z); l.z = tf32_rna(v.z - h.z);
            h.w = tf32_rna(v.w); l.w = tf32_rna(v.w - h.w);
            *(float4*)(Bh + kk * B_STRIDE + n4 * 4) = h;
            *(float4*)(Bl + kk * B_STRIDE + n4 * 4) = l;
        }
        __syncthreads();

        // ---- compute 4 k8-steps ----
#pragma unroll
        for (int s = 0; s < 4; ++s) {
            const int ks = s * 8;
            uint32_t ahi[2][4], alo[2][4];
#pragma unroll
            for (int mt = 0; mt < 2; ++mt) {
                int r = mw * 32 + mt * 16 + gID;
                ahi[mt][0] = __float_as_uint(Ah[r * A_STRIDE + ks + tig]);
                ahi[mt][1] = __float_as_uint(Ah[(r + 8) * A_STRIDE + ks + tig]);
                ahi[mt][2] = __float_as_uint(Ah[r * A_STRIDE + ks + tig + 4]);
                ahi[mt][3] = __float_as_uint(Ah[(r + 8) * A_STRIDE + ks + tig + 4]);
                alo[mt][0] = __float_as_uint(Al[r * A_STRIDE + ks + tig]);
                alo[mt][1] = __float_as_uint(Al[(r + 8) * A_STRIDE + ks + tig]);
                alo[mt][2] = __float_as_uint(Al[r * A_STRIDE + ks + tig + 4]);
                alo[mt][3] = __float_as_uint(Al[(r + 8) * A_STRIDE + ks + tig + 4]);
            }
#pragma unroll
            for (int nt = 0; nt < 8; ++nt) {
                int col = nw * 64 + nt * 8 + gID;
                uint32_t b0h = __float_as_uint(Bh[(ks + tig) * B_STRIDE + col]);
                uint32_t b1h = __float_as_uint(Bh[(ks + tig + 4) * B_STRIDE + col]);
                uint32_t b0l = __float_as_uint(Bl[(ks + tig) * B_STRIDE + col]);
                uint32_t b1l = __float_as_uint(Bl[(ks + tig + 4) * B_STRIDE + col]);
#pragma unroll
                for (int mt = 0; mt < 2; ++mt) {
                    mma_tf32(acc[mt][nt], ahi[mt], b0h, b1h);
                    mma_tf32(acc[mt][nt], ahi[mt], b0l, b1l);
                    mma_tf32(acc[mt][nt], alo[mt], b0h, b1h);
                }
            }
        }
    }

    // ---- epilogue on C fragments ----
    // c0: (row=gID, col=tig*2), c1: col+1, c2: row+8, c3: row+8 col+1
    float2 w2v[8];
#pragma unroll
    for (int nt = 0; nt < 8; ++nt)
        w2v[nt] = *(float2*)(w2_s + nw * 64 + nt * 8 + tig * 2);

    const int q = nh * 2 + nw;     // partial slot
#pragma unroll
    for (int b = 0; b < BB; ++b) {
        float s00 = 0.f, s01 = 0.f, s10 = 0.f, s11 = 0.f;
#pragma unroll
        for (int nt = 0; nt < 8; ++nt) {
            float2 p2 = *(float2*)(ph_s + b * 128 + nw * 64 + nt * 8 + tig * 2);
            float wx = w2v[nt].x, wy = w2v[nt].y;
            s00 = fmaf(fmaxf(acc[0][nt][0] + p2.x, 0.f), wx, s00);
            s00 = fmaf(fmaxf(acc[0][nt][1] + p2.y, 0.f), wy, s00);
            s01 = fmaf(fmaxf(acc[0][nt][2] + p2.x, 0.f), wx, s01);
            s01 = fmaf(fmaxf(acc[0][nt][3] + p2.y, 0.f), wy, s01);
            s10 = fmaf(fmaxf(acc[1][nt][0] + p2.x, 0.f), wx, s10);
            s10 = fmaf(fmaxf(acc[1][nt][1] + p2.y, 0.f), wy, s10);
            s11 = fmaf(fmaxf(acc[1][nt][2] + p2.x, 0.f), wx, s11);
            s11 = fmaf(fmaxf(acc[1][nt][3] + p2.y, 0.f), wy, s11);
        }
#pragma unroll
        for (int off = 1; off <= 2; off <<= 1) {
            s00 += __shfl_xor_sync(0xffffffffu, s00, off);
            s01 += __shfl_xor_sync(0xffffffffu, s01, off);
            s10 += __shfl_xor_sync(0xffffffffu, s10, off);
            s11 += __shfl_xor_sync(0xffffffffu, s11, off);
        }
        if (tig == 0) {
            int r0 = e_base + mw * 32 + gID;          // mt=0 row, +8
            int r1 = e_base + mw * 32 + 16 + gID;     // mt=1 row, +8
            if (r0 < E_TOT)     g_part[q][b][r0]      = s00;
            if (r0 + 8 < E_TOT) g_part[q][b][r0 + 8]  = s01;
            if (r1 < E_TOT)     g_part[q][b][r1]      = s10;
            if (r1 + 8 < E_TOT) g_part[q][b][r1 + 8]  = s11;
        }
    }
}

// ---------------------------------------------------------------------------
// Kernel 3a: per-(batch, chunk) top-10, summing the 4 partials + b2.
// ---------------------------------------------------------------------------
__global__ void topk1_kernel(const float* __restrict__ b2) {
    const int b = blockIdx.x;
    const int c = blockIdx.y;
    const int tid = threadIdx.x;
    const int cbeg = c * (E_TOT / NCHUNK);
    const int cend = cbeg + (E_TOT / NCHUNK);
    const float b2v = b2[0];

    float sc[KTOP];
    int   si[KTOP];
#pragma unroll
    for (int j = 0; j < KTOP; ++j) { sc[j] = -CUDART_INF_F; si[j] = 0x7fffffff; }

    for (int e = cbeg + tid; e < cend; e += 256) {
        float s = (g_part[0][b][e] + g_part[1][b][e]) +
                  (g_part[2][b][e] + g_part[3][b][e]) + b2v;
        if (s > sc[KTOP - 1]) {
            int p = KTOP - 1;
            while (p > 0 && s > sc[p - 1]) { sc[p] = sc[p - 1]; si[p] = si[p - 1]; --p; }
            sc[p] = s; si[p] = e;
        }
    }

    __shared__ float ssc[256 * KTOP];
    __shared__ int   ssi[256 * KTOP];
#pragma unroll
    for (int j = 0; j < KTOP; ++j) { ssc[tid * KTOP + j] = sc[j]; ssi[tid * KTOP + j] = si[j]; }
    __syncthreads();

    for (int stride = 128; stride > 0; stride >>= 1) {
        if (tid < stride) {
            float* A  = &ssc[tid * KTOP];
            int*   Ai = &ssi[tid * KTOP];
            float* Bv = &ssc[(tid + stride) * KTOP];
            int*   Bi = &ssi[(tid + stride) * KTOP];
            float msc[KTOP]; int msi[KTOP];
            int p = 0, qq = 0;
#pragma unroll
            for (int j = 0; j < KTOP; ++j) {
                bool takeA = (A[p] > Bv[qq]) || (A[p] == Bv[qq] && Ai[p] < Bi[qq]);
                if (takeA) { msc[j] = A[p]; msi[j] = Ai[p]; ++p; }
                else       { msc[j] = Bv[qq]; msi[j] = Bi[qq]; ++qq; }
            }
#pragma unroll
            for (int j = 0; j < KTOP; ++j) { A[j] = msc[j]; Ai[j] = msi[j]; }
        }
        __syncthreads();
    }

    if (tid < KTOP) {
        g_cs[(b * NCHUNK + c) * KTOP + tid] = ssc[tid];
        g_ci[(b * NCHUNK + c) * KTOP + tid] = ssi[tid];
    }
}

// ---------------------------------------------------------------------------
// Kernel 3b: single block, warp-per-batch bitonic over 160 candidates.
// ---------------------------------------------------------------------------
__global__ void topk2_kernel(float* __restrict__ out) {
    __shared__ float ss[BB][256];
    __shared__ int   si[BB][256];
    const int w = threadIdx.x >> 5;
    const int l = threadIdx.x & 31;

#pragma unroll
    for (int q = 0; q < 8; ++q) {
        int s = q * 32 + l;
        if (s < NCHUNK * KTOP) {
            ss[w][s] = g_cs[w * NCHUNK * KTOP + s];
            si[w][s] = g_ci[w * NCHUNK * KTOP + s];
        } else {
            ss[w][s] = -CUDART_INF_F;
            si[w][s] = 0x7fffffff;
        }
    }
    __syncwarp();

    for (int k = 2; k <= 256; k <<= 1) {
        for (int j = k >> 1; j > 0; j >>= 1) {
#pragma unroll
            for (int q = 0; q < 8; ++q) {
                int idx = q * 32 + l;
                int ixj = idx ^ j;
                if (ixj > idx) {
                    bool up = ((idx & k) == 0);
                    float s1 = ss[w][idx], s2 = ss[w][ixj];
                    int   i1 = si[w][idx], i2 = si[w][ixj];
                    bool ahead = (s1 > s2) || (s1 == s2 && i1 < i2);
                    if (ahead != up) {
                        ss[w][idx] = s2; si[w][idx] = i2;
                        ss[w][ixj] = s1; si[w][ixj] = i1;
                    }
                }
            }
            __syncwarp();
        }
    }

    if (l < KTOP) {
        out[w * KTOP + l]             = (float)si[w][l];
        out[BB * KTOP + w * KTOP + l] = ss[w][l];
    }
}

// ---------------------------------------------------------------------------
extern "C" void kernel_launch(void* const* d_in, const int* in_sizes, int n_in,
                              void* d_out, int out_size) {
    int base = (n_in >= 3 && in_sizes[2] == 1) ? 3 : 2;

    const int*   head = (const int*)d_in[0];
    const int*   rel  = (const int*)d_in[1];
    const float* ent  = (const float*)d_in[base + 0];
    const float* relm = (const float*)d_in[base + 1];
    const float* W1   = (const float*)d_in[base + 2];
    const float* b1   = (const float*)d_in[base + 3];
    const float* W2   = (const float*)d_in[base + 4];
    const float* b2   = (const float*)d_in[base + 5];
    float* out = (float*)d_out;

    size_t smem_bytes = SM_TOT_F * sizeof(float);   // ~76.3 KB
    cudaFuncSetAttribute(score_kernel, cudaFuncAttributeMaxDynamicSharedMemorySize,
                         (int)smem_bytes);

    ph_kernel<<<dim3(BB, 4), 256>>>(head, rel, ent, relm, W1, b1);
    score_kernel<<<dim3(N_TILES, 2), 256, smem_bytes>>>(ent, W1, W2);
    topk1_kernel<<<dim3(BB, NCHUNK), 256>>>(b2);
    topk2_kernel<<<1, 256>>>(out);
}